// round 3
// baseline (speedup 1.0000x reference)
#include <cuda_runtime.h>
#include <cstdint>

#define B   64
#define N   65536
#define CPB 32                 // CTAs per batch for wide passes
#define TH  256
#define CHUNK (N / CPB)        // 2048 points per CTA
#define PPT   (CHUNK / TH)     // 8 points per thread
#define WIDE  (B * CPB)        // 2048 CTAs

// ---- __device__ scratch (allocation-free rule) ----
__device__ float2   g_xy[B * N];           // packed xy (32 MB)
__device__ float    g_z[B * N];            // packed z  (16 MB)
__device__ float    g_pv[WIDE];            // partial argmax values
__device__ int      g_pi[WIDE];            // partial argmax indices (global)
__device__ float4   g_cent[B * 4];         // centers (xyz, pad)
__device__ unsigned g_bits[B * N / 32];    // keep bitmask (512 KB)
__device__ int      g_idx[B * N];          // compacted kept indices
__device__ int      g_nv[B];               // num_valid per batch

// warp argmax: value desc, index asc on ties
__device__ __forceinline__ void warp_argmax(float& best, int& bi) {
    #pragma unroll
    for (int o = 16; o; o >>= 1) {
        const float v = __shfl_down_sync(0xffffffffu, best, o);
        const int   j = __shfl_down_sync(0xffffffffu, bi,   o);
        if (v > best || (v == best && j < bi)) { best = v; bi = j; }
    }
}

// block-level partial argmax -> g_pv/g_pi[slot]
__device__ __forceinline__ void block_partial_out(float best, int bi, int slot) {
    __shared__ float sv[8];
    __shared__ int   si[8];
    const int lane = threadIdx.x & 31, w = threadIdx.x >> 5;
    warp_argmax(best, bi);
    if (lane == 0) { sv[w] = best; si[w] = bi; }
    __syncthreads();
    if (threadIdx.x < 8) {
        best = sv[threadIdx.x]; bi = si[threadIdx.x];
        #pragma unroll
        for (int o = 4; o; o >>= 1) {
            const float v = __shfl_down_sync(0xffu, best, o);
            const int   j = __shfl_down_sync(0xffu, bi,   o);
            if (v > best || (v == best && j < bi)) { best = v; bi = j; }
        }
        if (threadIdx.x == 0) { g_pv[slot] = best; g_pi[slot] = bi; }
    }
}

// Pass 1: smem-staged coalesced read of raw rows; pack xy/z; dist^2 to
// center 0; partial argmax -> center 1 candidates.
__global__ __launch_bounds__(TH) void pack_kernel(const float* __restrict__ pts) {
    __shared__ float4 sbuf[CHUNK * 6 / 4];          // 3072 float4 = 48 KB
    const int b   = blockIdx.x / CPB;
    const int cta = blockIdx.x % CPB;
    const float* P = pts + (size_t)b * N * 6;
    const float4* src = (const float4*)(P + (size_t)cta * CHUNK * 6);

    for (int i = threadIdx.x; i < CHUNK * 6 / 4; i += TH) sbuf[i] = src[i];
    const float c0x = P[0], c0y = P[1], c0z = P[2];  // center 0 = point 0
    __syncthreads();

    const float* sf = (const float*)sbuf;
    float best = -1.0f; int bi = 0;
    #pragma unroll
    for (int k = 0; k < PPT; k++) {
        const int r  = threadIdx.x + k * TH;        // strided: coalesced writes
        const int gi = b * N + cta * CHUNK + r;
        const float x = sf[r * 6], y = sf[r * 6 + 1], z = sf[r * 6 + 2];
        g_xy[gi] = make_float2(x, y);
        g_z[gi]  = z;
        const float dx = x - c0x, dy = y - c0y, dz = z - c0z;
        const float md = dx * dx + dy * dy + dz * dz;
        if (md > best) { best = md; bi = gi; }
    }
    block_partial_out(best, bi, blockIdx.x);
    if (cta == 0 && threadIdx.x == 0) g_cent[b * 4] = make_float4(c0x, c0y, c0z, 0.f);
}

// FPS step s: every CTA reduces its batch's 32 partials -> center s
// (redundantly, no extra launch), then min-dist over centers 0..s,
// partial argmax -> center s+1 candidates. cta 0 persists center s.
__global__ __launch_bounds__(TH) void step_kernel(int s) {
    const int b   = blockIdx.x / CPB;
    const int cta = blockIdx.x % CPB;
    __shared__ float4 sc[4];

    if (threadIdx.x < 32) {
        float v = g_pv[b * CPB + threadIdx.x];
        int   j = g_pi[b * CPB + threadIdx.x];
        warp_argmax(v, j);
        if (threadIdx.x == 0) {
            const float2 xy = g_xy[j];
            sc[s] = make_float4(xy.x, xy.y, g_z[j], 0.f);
            if (cta == 0) g_cent[b * 4 + s] = sc[s];
        }
    }
    if (threadIdx.x < s) sc[threadIdx.x] = g_cent[b * 4 + threadIdx.x];
    __syncthreads();

    float best = -1.0f; int bi = 0;
    #pragma unroll
    for (int k = 0; k < PPT; k++) {
        const int gi = b * N + cta * CHUNK + threadIdx.x + k * TH;
        const float2 xy = g_xy[gi];
        const float  z  = g_z[gi];
        float md = 1e10f;
        for (int cc = 0; cc <= s; cc++) {
            const float dx = xy.x - sc[cc].x;
            const float dy = xy.y - sc[cc].y;
            const float dz = z    - sc[cc].z;
            md = fminf(md, dx * dx + dy * dy + dz * dz);
        }
        if (md > best) { best = md; bi = gi; }
    }
    block_partial_out(best, bi, blockIdx.x);
}

// Keep bitmask: reduce step(2) partials -> center 3 in-CTA, then
// bit set iff sqrt(min dist^2 to 4 centers) >= 0.2.
__global__ __launch_bounds__(TH) void mask_kernel() {
    const int gi = blockIdx.x * TH + threadIdx.x;   // one thread per point
    const int b  = gi >> 16;                        // constant per CTA (256 CTAs/batch)
    __shared__ float4 sc[4];

    if (threadIdx.x < 32) {
        float v = g_pv[b * CPB + threadIdx.x];
        int   j = g_pi[b * CPB + threadIdx.x];
        warp_argmax(v, j);
        if (threadIdx.x == 0) {
            const float2 xy = g_xy[j];
            sc[3] = make_float4(xy.x, xy.y, g_z[j], 0.f);
        }
    }
    if (threadIdx.x < 3) sc[threadIdx.x] = g_cent[b * 4 + threadIdx.x];
    __syncthreads();

    const float2 xy = g_xy[gi];
    const float  z  = g_z[gi];
    float md = 1e10f;
    #pragma unroll
    for (int cc = 0; cc < 4; cc++) {
        const float dx = xy.x - sc[cc].x;
        const float dy = xy.y - sc[cc].y;
        const float dz = z    - sc[cc].z;
        md = fminf(md, dx * dx + dy * dy + dz * dz);
    }
    const bool keep = (__fsqrt_rn(md) >= 0.2f);
    const unsigned w = __ballot_sync(0xffffffffu, keep);
    if ((threadIdx.x & 31) == 0) g_bits[gi >> 5] = w;
}

// Stable compaction: one block per batch over the bitmask.
__global__ __launch_bounds__(1024) void compact_kernel() {
    const int b = blockIdx.x;
    const int t = threadIdx.x;
    const unsigned* mb = g_bits + b * (N / 32);
    const unsigned w0 = mb[t * 2], w1 = mb[t * 2 + 1];
    int cnt = __popc(w0) + __popc(w1);

    __shared__ int swarp[32];
    const int lane = t & 31, w = t >> 5;
    int inc = cnt;
    #pragma unroll
    for (int o = 1; o < 32; o <<= 1) {
        const int u = __shfl_up_sync(0xffffffffu, inc, o);
        if (lane >= o) inc += u;
    }
    if (lane == 31) swarp[w] = inc;
    __syncthreads();
    if (t < 32) {
        int v2 = swarp[t];
        #pragma unroll
        for (int o = 1; o < 32; o <<= 1) {
            const int u = __shfl_up_sync(0xffffffffu, v2, o);
            if (t >= o) v2 += u;
        }
        swarp[t] = v2;
    }
    __syncthreads();

    int off = inc - cnt + (w ? swarp[w - 1] : 0);
    int* ob = g_idx + b * N;
    const int base = t * 64;
    unsigned m = w0;
    while (m) { const int l = __ffs(m) - 1; m &= m - 1; ob[off++] = base + l; }
    m = w1;
    while (m) { const int l = __ffs(m) - 1; m &= m - 1; ob[off++] = base + 32 + l; }
    if (t == 0) g_nv[b] = swarp[31];
}

// Two rows per thread: 48 B output = 3 coalesced float4 stores.
__global__ __launch_bounds__(TH) void gather_kernel(const float* __restrict__ pts,
                                                    float* __restrict__ out) {
    const int tid = blockIdx.x * TH + threadIdx.x;       // [0, B*N/2)
    const int b   = tid / (N / 2);
    const int jr  = (tid - b * (N / 2)) * 2;             // first of 2 rows
    const int nv  = g_nv[b];
    float4* dst = (float4*)(out + ((size_t)b * N + jr) * 6);

    if (nv == 0) {
        const float4 z4 = make_float4(0.f, 0.f, 0.f, 0.f);
        dst[0] = z4; dst[1] = z4; dst[2] = z4;
        return;
    }
    const int k0 = jr % nv;
    const int k1 = (k0 + 1 == nv) ? 0 : k0 + 1;
    const int s0 = g_idx[(b << 16) + k0];
    const int s1 = g_idx[(b << 16) + k1];
    const float* p0 = pts + ((size_t)(b << 16) + s0) * 6;
    const float* p1 = pts + ((size_t)(b << 16) + s1) * 6;
    const float2 a0 = *(const float2*)p0;
    const float2 a1 = *(const float2*)(p0 + 2);
    const float2 a2 = *(const float2*)(p0 + 4);
    const float2 b0 = *(const float2*)p1;
    const float2 b1 = *(const float2*)(p1 + 2);
    const float2 b2 = *(const float2*)(p1 + 4);
    dst[0] = make_float4(a0.x, a0.y, a1.x, a1.y);
    dst[1] = make_float4(a2.x, a2.y, b0.x, b0.y);
    dst[2] = make_float4(b1.x, b1.y, b2.x, b2.y);
}

extern "C" void kernel_launch(void* const* d_in, const int* in_sizes, int n_in,
                              void* d_out, int out_size) {
    const float* pts = (const float*)d_in[0];
    float* out = (float*)d_out;

    pack_kernel<<<WIDE, TH>>>(pts);        // -> partials for center 1
    step_kernel<<<WIDE, TH>>>(1);          // center 1, -> partials for center 2
    step_kernel<<<WIDE, TH>>>(2);          // center 2, -> partials for center 3
    mask_kernel<<<B * N / TH, TH>>>();     // center 3 + keep bits
    compact_kernel<<<B, 1024>>>();
    gather_kernel<<<(B * N / 2) / TH, TH>>>(pts, out);
}

// round 4
// speedup vs baseline: 1.0774x; 1.0774x over previous
#include <cuda_runtime.h>
#include <cstdint>

#define B   64
#define N   65536
#define CPB 32                 // CTAs per batch for wide passes
#define TH  256
#define CHUNK (N / CPB)        // 2048 points per CTA
#define PPT   (CHUNK / TH)     // 8 points per thread
#define WIDE  (B * CPB)        // 2048 CTAs

// ---- __device__ scratch (allocation-free rule) ----
__device__ float2   g_xy[B * N];           // packed xy (32 MB)
__device__ float    g_z[B * N];            // packed z  (16 MB)
__device__ float    g_pv[WIDE];            // partial argmax values
__device__ int      g_pi[WIDE];            // partial argmax indices (global)
__device__ float4   g_cent[B * 4];         // centers (xyz, pad)
__device__ unsigned g_bits[B * N / 32];    // keep bitmask (512 KB)
__device__ int      g_idx[B * N];          // compacted kept indices
__device__ int      g_nv[B];               // num_valid per batch

// warp argmax: value desc, index asc on ties
__device__ __forceinline__ void warp_argmax(float& best, int& bi) {
    #pragma unroll
    for (int o = 16; o; o >>= 1) {
        const float v = __shfl_down_sync(0xffffffffu, best, o);
        const int   j = __shfl_down_sync(0xffffffffu, bi,   o);
        if (v > best || (v == best && j < bi)) { best = v; bi = j; }
    }
}

// block-level partial argmax -> g_pv/g_pi[slot]
__device__ __forceinline__ void block_partial_out(float best, int bi, int slot) {
    __shared__ float sv[8];
    __shared__ int   si[8];
    const int lane = threadIdx.x & 31, w = threadIdx.x >> 5;
    warp_argmax(best, bi);
    if (lane == 0) { sv[w] = best; si[w] = bi; }
    __syncthreads();
    if (threadIdx.x < 8) {
        best = sv[threadIdx.x]; bi = si[threadIdx.x];
        #pragma unroll
        for (int o = 4; o; o >>= 1) {
            const float v = __shfl_down_sync(0xffu, best, o);
            const int   j = __shfl_down_sync(0xffu, bi,   o);
            if (v > best || (v == best && j < bi)) { best = v; bi = j; }
        }
        if (threadIdx.x == 0) { g_pv[slot] = best; g_pi[slot] = bi; }
    }
}

// Pass 1: smem-staged coalesced read of raw rows; pack xy/z; dist^2 to
// center 0; partial argmax -> center 1 candidates.
__global__ __launch_bounds__(TH) void pack_kernel(const float* __restrict__ pts) {
    __shared__ float4 sbuf[CHUNK * 6 / 4];          // 3072 float4 = 48 KB
    const int b   = blockIdx.x / CPB;
    const int cta = blockIdx.x % CPB;
    const float* P = pts + (size_t)b * N * 6;
    const float4* src = (const float4*)(P + (size_t)cta * CHUNK * 6);

    for (int i = threadIdx.x; i < CHUNK * 6 / 4; i += TH) sbuf[i] = src[i];
    const float c0x = P[0], c0y = P[1], c0z = P[2];  // center 0 = point 0
    __syncthreads();

    const float* sf = (const float*)sbuf;
    float best = -1.0f; int bi = 0;
    #pragma unroll
    for (int k = 0; k < PPT; k++) {
        const int r  = threadIdx.x + k * TH;        // strided: coalesced writes
        const int gi = b * N + cta * CHUNK + r;
        const float x = sf[r * 6], y = sf[r * 6 + 1], z = sf[r * 6 + 2];
        g_xy[gi] = make_float2(x, y);
        g_z[gi]  = z;
        const float dx = x - c0x, dy = y - c0y, dz = z - c0z;
        const float md = dx * dx + dy * dy + dz * dz;
        if (md > best) { best = md; bi = gi; }
    }
    block_partial_out(best, bi, blockIdx.x);
    if (cta == 0 && threadIdx.x == 0) g_cent[b * 4] = make_float4(c0x, c0y, c0z, 0.f);
}

// FPS step s: every CTA reduces its batch's 32 partials -> center s
// (redundantly, no extra launch), then min-dist over centers 0..s,
// partial argmax -> center s+1 candidates. cta 0 persists center s.
__global__ __launch_bounds__(TH) void step_kernel(int s) {
    const int b   = blockIdx.x / CPB;
    const int cta = blockIdx.x % CPB;
    __shared__ float4 sc[4];

    if (threadIdx.x < 32) {
        float v = g_pv[b * CPB + threadIdx.x];
        int   j = g_pi[b * CPB + threadIdx.x];
        warp_argmax(v, j);
        if (threadIdx.x == 0) {
            const float2 xy = g_xy[j];
            sc[s] = make_float4(xy.x, xy.y, g_z[j], 0.f);
            if (cta == 0) g_cent[b * 4 + s] = sc[s];
        }
    }
    if (threadIdx.x < s) sc[threadIdx.x] = g_cent[b * 4 + threadIdx.x];
    __syncthreads();

    float best = -1.0f; int bi = 0;
    #pragma unroll
    for (int k = 0; k < PPT; k++) {
        const int gi = b * N + cta * CHUNK + threadIdx.x + k * TH;
        const float2 xy = g_xy[gi];
        const float  z  = g_z[gi];
        float md = 1e10f;
        for (int cc = 0; cc <= s; cc++) {
            const float dx = xy.x - sc[cc].x;
            const float dy = xy.y - sc[cc].y;
            const float dz = z    - sc[cc].z;
            md = fminf(md, dx * dx + dy * dy + dz * dz);
        }
        if (md > best) { best = md; bi = gi; }
    }
    block_partial_out(best, bi, blockIdx.x);
}

// Keep bitmask (WIDE shape, 8 pts/thread): reduce step(2) partials ->
// center 3 in-CTA (amortized over 2048 points), then per-point
// keep = (sqrt(min dist^2 to 4 centers) >= 0.2); ballot -> bitmask.
__global__ __launch_bounds__(TH) void mask_kernel() {
    const int b   = blockIdx.x / CPB;
    const int cta = blockIdx.x % CPB;
    __shared__ float4 sc[4];

    if (threadIdx.x < 32) {
        float v = g_pv[b * CPB + threadIdx.x];
        int   j = g_pi[b * CPB + threadIdx.x];
        warp_argmax(v, j);
        if (threadIdx.x == 0) {
            const float2 xy = g_xy[j];
            sc[3] = make_float4(xy.x, xy.y, g_z[j], 0.f);
        }
    }
    if (threadIdx.x < 3) sc[threadIdx.x] = g_cent[b * 4 + threadIdx.x];
    __syncthreads();

    const float4 c0 = sc[0], c1 = sc[1], c2 = sc[2], c3 = sc[3];
    #pragma unroll
    for (int k = 0; k < PPT; k++) {
        const int gi = b * N + cta * CHUNK + threadIdx.x + k * TH;  // lanes consecutive
        const float2 xy = g_xy[gi];
        const float  z  = g_z[gi];
        float dx = xy.x - c0.x, dy = xy.y - c0.y, dz = z - c0.z;
        float md = fminf(1e10f, dx * dx + dy * dy + dz * dz);
        dx = xy.x - c1.x; dy = xy.y - c1.y; dz = z - c1.z;
        md = fminf(md, dx * dx + dy * dy + dz * dz);
        dx = xy.x - c2.x; dy = xy.y - c2.y; dz = z - c2.z;
        md = fminf(md, dx * dx + dy * dy + dz * dz);
        dx = xy.x - c3.x; dy = xy.y - c3.y; dz = z - c3.z;
        md = fminf(md, dx * dx + dy * dy + dz * dz);
        const bool keep = (__fsqrt_rn(md) >= 0.2f);
        const unsigned w = __ballot_sync(0xffffffffu, keep);
        if ((threadIdx.x & 31) == 0) g_bits[gi >> 5] = w;
    }
}

// Stable compaction: one block per batch over the bitmask.
__global__ __launch_bounds__(1024) void compact_kernel() {
    const int b = blockIdx.x;
    const int t = threadIdx.x;
    const unsigned* mb = g_bits + b * (N / 32);
    const unsigned w0 = mb[t * 2], w1 = mb[t * 2 + 1];
    int cnt = __popc(w0) + __popc(w1);

    __shared__ int swarp[32];
    const int lane = t & 31, w = t >> 5;
    int inc = cnt;
    #pragma unroll
    for (int o = 1; o < 32; o <<= 1) {
        const int u = __shfl_up_sync(0xffffffffu, inc, o);
        if (lane >= o) inc += u;
    }
    if (lane == 31) swarp[w] = inc;
    __syncthreads();
    if (t < 32) {
        int v2 = swarp[t];
        #pragma unroll
        for (int o = 1; o < 32; o <<= 1) {
            const int u = __shfl_up_sync(0xffffffffu, v2, o);
            if (t >= o) v2 += u;
        }
        swarp[t] = v2;
    }
    __syncthreads();

    int off = inc - cnt + (w ? swarp[w - 1] : 0);
    int* ob = g_idx + b * N;
    const int base = t * 64;
    unsigned m = w0;
    while (m) { const int l = __ffs(m) - 1; m &= m - 1; ob[off++] = base + l; }
    m = w1;
    while (m) { const int l = __ffs(m) - 1; m &= m - 1; ob[off++] = base + 32 + l; }
    if (t == 0) g_nv[b] = swarp[31];
}

// Two rows per thread: 48 B output = 3 coalesced float4 stores.
__global__ __launch_bounds__(TH) void gather_kernel(const float* __restrict__ pts,
                                                    float* __restrict__ out) {
    const int tid = blockIdx.x * TH + threadIdx.x;       // [0, B*N/2)
    const int b   = tid / (N / 2);
    const int jr  = (tid - b * (N / 2)) * 2;             // first of 2 rows
    const int nv  = g_nv[b];
    float4* dst = (float4*)(out + ((size_t)b * N + jr) * 6);

    if (nv == 0) {
        const float4 z4 = make_float4(0.f, 0.f, 0.f, 0.f);
        dst[0] = z4; dst[1] = z4; dst[2] = z4;
        return;
    }
    const int k0 = jr % nv;
    const int k1 = (k0 + 1 == nv) ? 0 : k0 + 1;
    const int s0 = g_idx[(b << 16) + k0];
    const int s1 = g_idx[(b << 16) + k1];
    const float* p0 = pts + ((size_t)(b << 16) + s0) * 6;
    const float* p1 = pts + ((size_t)(b << 16) + s1) * 6;
    const float2 a0 = *(const float2*)p0;
    const float2 a1 = *(const float2*)(p0 + 2);
    const float2 a2 = *(const float2*)(p0 + 4);
    const float2 b0 = *(const float2*)p1;
    const float2 b1 = *(const float2*)(p1 + 2);
    const float2 b2 = *(const float2*)(p1 + 4);
    dst[0] = make_float4(a0.x, a0.y, a1.x, a1.y);
    dst[1] = make_float4(a2.x, a2.y, b0.x, b0.y);
    dst[2] = make_float4(b1.x, b1.y, b2.x, b2.y);
}

extern "C" void kernel_launch(void* const* d_in, const int* in_sizes, int n_in,
                              void* d_out, int out_size) {
    const float* pts = (const float*)d_in[0];
    float* out = (float*)d_out;

    pack_kernel<<<WIDE, TH>>>(pts);        // -> partials for center 1
    step_kernel<<<WIDE, TH>>>(1);          // center 1, -> partials for center 2
    step_kernel<<<WIDE, TH>>>(2);          // center 2, -> partials for center 3
    mask_kernel<<<WIDE, TH>>>();           // center 3 + keep bits
    compact_kernel<<<B, 1024>>>();
    gather_kernel<<<(B * N / 2) / TH, TH>>>(pts, out);
}

// round 5
// speedup vs baseline: 1.1774x; 1.0929x over previous
#include <cuda_runtime.h>
#include <cstdint>

#define B    64
#define N    65536
#define GRID 128              // 2 CTAs per batch; 128 <= 148 SMs -> all resident
#define TH   1024
#define HALFN (N / 2)         // 32768 points per CTA
#define PPT  (HALFN / TH)     // 32 points per thread

// ---- __device__ scratch (allocation-free rule) ----
__device__ float2   g_xy[B * N];            // packed xy (32 MB)
__device__ float    g_z[B * N];             // packed z  (16 MB)
__device__ float    g_pv[2 * GRID];         // partial argmax values (double-buffered)
__device__ int      g_pi[2 * GRID];         // partial argmax indices (global ids)
__device__ unsigned g_bits[B * N / 32];     // keep bitmask (512 KB)
__device__ int      g_idx[B * N];           // compacted kept indices
__device__ int      g_nv[B];                // num_valid per batch
__device__ unsigned g_count;                // barrier arrive counter (self-resetting)
__device__ unsigned g_gen;                  // barrier generation (monotonic)

// Grid-wide barrier: all GRID CTAs are resident (1/SM), so spinning is safe.
__device__ __forceinline__ void grid_sync() {
    __syncthreads();
    if (threadIdx.x == 0) {
        __threadfence();
        const unsigned gen = atomicAdd(&g_gen, 0u);
        if (atomicAdd(&g_count, 1u) == GRID - 1u) {
            g_count = 0u;
            __threadfence();
            atomicAdd(&g_gen, 1u);          // release
        } else {
            while (atomicAdd(&g_gen, 0u) == gen) { __nanosleep(64); }
        }
        __threadfence();
    }
    __syncthreads();
}

// warp argmax: value desc, index asc on ties
__device__ __forceinline__ void warp_argmax(float& best, int& bi) {
    #pragma unroll
    for (int o = 16; o; o >>= 1) {
        const float v = __shfl_down_sync(0xffffffffu, best, o);
        const int   j = __shfl_down_sync(0xffffffffu, bi,   o);
        if (v > best || (v == best && j < bi)) { best = v; bi = j; }
    }
}

// block partial argmax (1024 threads) -> g_pv/g_pi[buf*GRID + cta]
__device__ __forceinline__ void block_partial(float best, int bi, int buf,
                                              float* sv, int* si) {
    const int lane = threadIdx.x & 31, w = threadIdx.x >> 5;
    warp_argmax(best, bi);
    if (lane == 0) { sv[w] = best; si[w] = bi; }
    __syncthreads();
    if (threadIdx.x < 32) {
        best = sv[threadIdx.x]; bi = si[threadIdx.x];
        warp_argmax(best, bi);
        if (threadIdx.x == 0) {
            g_pv[buf * GRID + blockIdx.x] = best;
            g_pi[buf * GRID + blockIdx.x] = bi;
        }
    }
    __syncthreads();   // sv/si reused by later phases
}

__global__ __launch_bounds__(TH, 1) void mega_kernel(const float* __restrict__ pts,
                                                     float* __restrict__ out) {
    const int cta  = blockIdx.x;
    const int b    = cta >> 1;
    const int half = cta & 1;
    const int base = half * HALFN;                   // batch-local start
    const float* P = pts + (size_t)b * N * 6;
    const int t = threadIdx.x;

    __shared__ float4 sc[4];
    __shared__ float  sv[32];
    __shared__ int    si[32];
    __shared__ int    swarp[32];

    // ================= Phase 0: pack + dist^2 to center 0 =================
    const float c0x = P[0], c0y = P[1], c0z = P[2];  // center 0 = point 0
    if (t == 0) sc[0] = make_float4(c0x, c0y, c0z, 0.f);
    {
        float best = -1.0f; int bi = 0;
        #pragma unroll 8
        for (int k = 0; k < PPT; k++) {
            const int il = base + t + k * TH;        // strided: coalesced
            const int gi = b * N + il;
            const float* p = P + (size_t)il * 6;
            const float2 xy = *(const float2*)p;     // rows 24B -> 8B aligned
            const float  z  = p[2];
            g_xy[gi] = xy;
            g_z[gi]  = z;
            const float dx = xy.x - c0x, dy = xy.y - c0y, dz = z - c0z;
            const float md = dx * dx + dy * dy + dz * dz;
            if (md > best) { best = md; bi = gi; }   // strict >: min-index ties
        }
        block_partial(best, bi, /*buf=*/0, sv, si);
    }
    grid_sync();

    // ================= Phases 1,2: FPS steps; phase 3: final center ========
    for (int s = 1; s <= 3; s++) {
        // reduce this batch's 2 partials (prev phase buffer) -> center s
        const int rbuf = (s - 1) & 1;
        if (t == 0) {
            const float v0 = g_pv[rbuf * GRID + b * 2];
            const float v1 = g_pv[rbuf * GRID + b * 2 + 1];
            const int   j0 = g_pi[rbuf * GRID + b * 2];
            const int   j1 = g_pi[rbuf * GRID + b * 2 + 1];
            const int j = (v1 > v0 || (v1 == v0 && j1 < j0)) ? j1 : j0;
            const float2 xy = g_xy[j];
            sc[s] = make_float4(xy.x, xy.y, g_z[j], 0.f);
        }
        __syncthreads();
        if (s == 3) break;                            // all 4 centers known

        float best = -1.0f; int bi = 0;
        #pragma unroll 4
        for (int k = 0; k < PPT; k++) {
            const int gi = b * N + base + t + k * TH;
            const float2 xy = g_xy[gi];
            const float  z  = g_z[gi];
            float md = 1e10f;
            for (int cc = 0; cc <= s; cc++) {
                const float dx = xy.x - sc[cc].x;
                const float dy = xy.y - sc[cc].y;
                const float dz = z    - sc[cc].z;
                md = fminf(md, dx * dx + dy * dy + dz * dz);
            }
            if (md > best) { best = md; bi = gi; }
        }
        block_partial(best, bi, /*buf=*/s & 1, sv, si);
        grid_sync();
    }

    // ================= Phase 4: keep bitmask ===============================
    {
        const float4 cc0 = sc[0], cc1 = sc[1], cc2 = sc[2], cc3 = sc[3];
        #pragma unroll 4
        for (int k = 0; k < PPT; k++) {
            const int gi = b * N + base + t + k * TH;  // warp lanes consecutive
            const float2 xy = g_xy[gi];
            const float  z  = g_z[gi];
            float dx = xy.x - cc0.x, dy = xy.y - cc0.y, dz = z - cc0.z;
            float md = fminf(1e10f, dx * dx + dy * dy + dz * dz);
            dx = xy.x - cc1.x; dy = xy.y - cc1.y; dz = z - cc1.z;
            md = fminf(md, dx * dx + dy * dy + dz * dz);
            dx = xy.x - cc2.x; dy = xy.y - cc2.y; dz = z - cc2.z;
            md = fminf(md, dx * dx + dy * dy + dz * dz);
            dx = xy.x - cc3.x; dy = xy.y - cc3.y; dz = z - cc3.z;
            md = fminf(md, dx * dx + dy * dy + dz * dz);
            const bool keep = (__fsqrt_rn(md) >= 0.2f);
            const unsigned w = __ballot_sync(0xffffffffu, keep);
            if ((t & 31) == 0) g_bits[gi >> 5] = w;
        }
    }
    grid_sync();

    // ================= Phase 5: stable compaction (64 active CTAs) =========
    if (cta < B) {
        const unsigned* mb = g_bits + cta * (N / 32);
        const unsigned w0 = mb[t * 2], w1 = mb[t * 2 + 1];
        int cnt = __popc(w0) + __popc(w1);

        const int lane = t & 31, w = t >> 5;
        int inc = cnt;
        #pragma unroll
        for (int o = 1; o < 32; o <<= 1) {
            const int u = __shfl_up_sync(0xffffffffu, inc, o);
            if (lane >= o) inc += u;
        }
        if (lane == 31) swarp[w] = inc;
        __syncthreads();
        if (t < 32) {
            int v2 = swarp[t];
            #pragma unroll
            for (int o = 1; o < 32; o <<= 1) {
                const int u = __shfl_up_sync(0xffffffffu, v2, o);
                if (t >= o) v2 += u;
            }
            swarp[t] = v2;
        }
        __syncthreads();

        int off = inc - cnt + (w ? swarp[w - 1] : 0);
        int* ob = g_idx + cta * N;
        const int bs = t * 64;
        unsigned m = w0;
        while (m) { const int l = __ffs(m) - 1; m &= m - 1; ob[off++] = bs + l; }
        m = w1;
        while (m) { const int l = __ffs(m) - 1; m &= m - 1; ob[off++] = bs + 32 + l; }
        if (t == 0) g_nv[cta] = swarp[31];
    }
    grid_sync();

    // ================= Phase 6: gather (2 rows/thread, float4 stores) ======
    {
        const int nv = g_nv[b];
        #pragma unroll 4
        for (int k = 0; k < PPT / 2; k++) {
            const int jr = base + (t + k * TH) * 2;        // first of 2 rows
            float4* dst = (float4*)(out + ((size_t)b * N + jr) * 6);
            if (nv == 0) {
                const float4 z4 = make_float4(0.f, 0.f, 0.f, 0.f);
                dst[0] = z4; dst[1] = z4; dst[2] = z4;
                continue;
            }
            const int k0 = jr % nv;
            const int k1 = (k0 + 1 == nv) ? 0 : k0 + 1;
            const int s0 = g_idx[(b << 16) + k0];
            const int s1 = g_idx[(b << 16) + k1];
            const float* p0 = pts + ((size_t)(b << 16) + s0) * 6;
            const float* p1 = pts + ((size_t)(b << 16) + s1) * 6;
            const float2 a0 = *(const float2*)p0;
            const float2 a1 = *(const float2*)(p0 + 2);
            const float2 a2 = *(const float2*)(p0 + 4);
            const float2 b0 = *(const float2*)p1;
            const float2 b1 = *(const float2*)(p1 + 2);
            const float2 b2 = *(const float2*)(p1 + 4);
            dst[0] = make_float4(a0.x, a0.y, a1.x, a1.y);
            dst[1] = make_float4(a2.x, a2.y, b0.x, b0.y);
            dst[2] = make_float4(b1.x, b1.y, b2.x, b2.y);
        }
    }
}

extern "C" void kernel_launch(void* const* d_in, const int* in_sizes, int n_in,
                              void* d_out, int out_size) {
    const float* pts = (const float*)d_in[0];
    float* out = (float*)d_out;
    mega_kernel<<<GRID, TH>>>(pts, out);
}

// round 6
// speedup vs baseline: 1.3457x; 1.1429x over previous
#include <cuda_runtime.h>
#include <cstdint>

#define B    64
#define N    65536
#define CPB  4                  // CTAs per batch
#define GRID (B * CPB)          // 256, all resident (148 SMs x 2)
#define TH   512
#define QN   (N / CPB)          // 16384 points per CTA
#define PPT  (QN / TH)          // 32 points per thread
#define WPB  (N / 32 / CPB)     // 512 bitmask words per CTA (== TH)

// ---- __device__ scratch (allocation-free rule) ----
__device__ float2   g_xy[B * N];            // packed xy (32 MB)
__device__ float    g_z[B * N];             // packed z  (16 MB)
__device__ float    g_pv[2 * GRID];         // partial argmax values (double-buffered)
__device__ int      g_pi[2 * GRID];         // partial argmax indices (global ids)
__device__ unsigned g_bits[B * N / 32];     // keep bitmask
__device__ int      g_idx[B * N];           // compacted kept indices
__device__ int      g_qtot[GRID];           // per-quarter keep counts
__device__ unsigned g_cnt[B];               // per-batch barrier counters
__device__ unsigned g_gen[B];               // per-batch barrier generations

// Per-batch barrier among the CPB CTAs of one batch. All CTAs resident.
__device__ __forceinline__ void batch_sync(int b) {
    __syncthreads();
    if (threadIdx.x == 0) {
        __threadfence();
        const unsigned gen = atomicAdd(&g_gen[b], 0u);
        if (atomicAdd(&g_cnt[b], 1u) == CPB - 1u) {
            atomicExch(&g_cnt[b], 0u);
            __threadfence();
            atomicAdd(&g_gen[b], 1u);                 // release
        } else {
            while (atomicAdd(&g_gen[b], 0u) == gen) { __nanosleep(32); }
        }
        __threadfence();
    }
    __syncthreads();
}

// warp argmax: value desc, index asc on ties
__device__ __forceinline__ void warp_argmax(float& best, int& bi) {
    #pragma unroll
    for (int o = 16; o; o >>= 1) {
        const float v = __shfl_down_sync(0xffffffffu, best, o);
        const int   j = __shfl_down_sync(0xffffffffu, bi,   o);
        if (v > best || (v == best && j < bi)) { best = v; bi = j; }
    }
}

// block partial argmax (512 threads) -> g_pv/g_pi[buf*GRID + cta]
__device__ __forceinline__ void block_partial(float best, int bi, int buf,
                                              float* sv, int* si) {
    const int t = threadIdx.x, lane = t & 31, w = t >> 5;
    warp_argmax(best, bi);
    if (lane == 0) { sv[w] = best; si[w] = bi; }
    __syncthreads();
    if (t < 16) {
        best = sv[t]; bi = si[t];
        #pragma unroll
        for (int o = 8; o; o >>= 1) {
            const float v = __shfl_down_sync(0xffffu, best, o);
            const int   j = __shfl_down_sync(0xffffu, bi,   o);
            if (v > best || (v == best && j < bi)) { best = v; bi = j; }
        }
        if (t == 0) {
            g_pv[buf * GRID + blockIdx.x] = best;
            g_pi[buf * GRID + blockIdx.x] = bi;
        }
    }
    __syncthreads();   // sv/si reused by later phases
}

__global__ __launch_bounds__(TH, 2) void mega_kernel(const float* __restrict__ pts,
                                                     float* __restrict__ out) {
    const int cta  = blockIdx.x;
    const int b    = cta / CPB;
    const int q    = cta % CPB;
    const int base = q * QN;                         // batch-local start
    const float* P = pts + (size_t)b * N * 6;
    const int t = threadIdx.x;

    __shared__ float4 sc[4];
    __shared__ float  sv[16];
    __shared__ int    si[16];
    __shared__ int    swarp[16];
    __shared__ int    sq[CPB];

    // ================= Phase 0: pack + dist^2 to center 0 =================
    const float c0x = P[0], c0y = P[1], c0z = P[2];  // center 0 = point 0
    if (t == 0) sc[0] = make_float4(c0x, c0y, c0z, 0.f);
    {
        float best = -1.0f; int bi = 0;
        #pragma unroll 8
        for (int k = 0; k < PPT; k++) {
            const int il = base + t + k * TH;        // strided: coalesced
            const int gi = b * N + il;
            const float* p = P + (size_t)il * 6;
            const float2 xy = *(const float2*)p;     // rows 24B -> 8B aligned
            const float  z  = p[2];
            g_xy[gi] = xy;
            g_z[gi]  = z;
            const float dx = xy.x - c0x, dy = xy.y - c0y, dz = z - c0z;
            const float md = dx * dx + dy * dy + dz * dz;
            if (md > best) { best = md; bi = gi; }   // strict >: min-index ties
        }
        block_partial(best, bi, /*buf=*/0, sv, si);
    }
    batch_sync(b);

    // ========== Phases 1,2: FPS steps; s==3 only resolves center 3 =========
    for (int s = 1; s <= 3; s++) {
        const int rbuf = (s - 1) & 1;                // buffer written by phase s-1
        if (t == 0) {
            float bv = g_pv[rbuf * GRID + b * CPB];
            int   bj = g_pi[rbuf * GRID + b * CPB];
            #pragma unroll
            for (int i = 1; i < CPB; i++) {
                const float v = g_pv[rbuf * GRID + b * CPB + i];
                const int   j = g_pi[rbuf * GRID + b * CPB + i];
                if (v > bv || (v == bv && j < bj)) { bv = v; bj = j; }
            }
            const float2 xy = g_xy[bj];
            sc[s] = make_float4(xy.x, xy.y, g_z[bj], 0.f);
        }
        __syncthreads();
        if (s == 3) break;                           // all 4 centers known

        float best = -1.0f; int bi = 0;
        #pragma unroll 4
        for (int k = 0; k < PPT; k++) {
            const int gi = b * N + base + t + k * TH;
            const float2 xy = g_xy[gi];
            const float  z  = g_z[gi];
            float md = 1e10f;
            for (int cc = 0; cc <= s; cc++) {
                const float dx = xy.x - sc[cc].x;
                const float dy = xy.y - sc[cc].y;
                const float dz = z    - sc[cc].z;
                md = fminf(md, dx * dx + dy * dy + dz * dz);
            }
            if (md > best) { best = md; bi = gi; }
        }
        block_partial(best, bi, /*buf=*/s & 1, sv, si);
        batch_sync(b);
    }

    // ================= Phase 3: keep bitmask ===============================
    {
        const float4 cc0 = sc[0], cc1 = sc[1], cc2 = sc[2], cc3 = sc[3];
        #pragma unroll 4
        for (int k = 0; k < PPT; k++) {
            const int gi = b * N + base + t + k * TH;  // warp lanes consecutive
            const float2 xy = g_xy[gi];
            const float  z  = g_z[gi];
            float dx = xy.x - cc0.x, dy = xy.y - cc0.y, dz = z - cc0.z;
            float md = fminf(1e10f, dx * dx + dy * dy + dz * dz);
            dx = xy.x - cc1.x; dy = xy.y - cc1.y; dz = z - cc1.z;
            md = fminf(md, dx * dx + dy * dy + dz * dz);
            dx = xy.x - cc2.x; dy = xy.y - cc2.y; dz = z - cc2.z;
            md = fminf(md, dx * dx + dy * dy + dz * dz);
            dx = xy.x - cc3.x; dy = xy.y - cc3.y; dz = z - cc3.z;
            md = fminf(md, dx * dx + dy * dy + dz * dz);
            const bool keep = (__fsqrt_rn(md) >= 0.2f);
            const unsigned wd = __ballot_sync(0xffffffffu, keep);
            if ((t & 31) == 0) g_bits[gi >> 5] = wd;
        }
    }
    batch_sync(b);

    // ======== Phase 4: stable compaction, split 4 ways per batch ===========
    int nv;                                          // num_valid (kept in regs)
    {
        // this CTA's quarter: 512 words, one per thread
        const unsigned wd = g_bits[b * (N / 32) + q * WPB + t];
        const int cnt = __popc(wd);

        const int lane = t & 31, w = t >> 5;
        int inc = cnt;
        #pragma unroll
        for (int o = 1; o < 32; o <<= 1) {
            const int u = __shfl_up_sync(0xffffffffu, inc, o);
            if (lane >= o) inc += u;
        }
        if (lane == 31) swarp[w] = inc;
        __syncthreads();
        if (t < 16) {
            int v2 = swarp[t];
            #pragma unroll
            for (int o = 1; o < 16; o <<= 1) {
                const int u = __shfl_up_sync(0xffffu, v2, o);
                if (t >= o) v2 += u;
            }
            swarp[t] = v2;
        }
        __syncthreads();
        const int off_local = inc - cnt + (w ? swarp[w - 1] : 0);
        if (t == 0) g_qtot[cta] = swarp[15];         // publish quarter total
        batch_sync(b);

        if (t < CPB) sq[t] = g_qtot[b * CPB + t];
        __syncthreads();
        int offset_base = 0;
        for (int i = 0; i < q; i++) offset_base += sq[i];
        nv = sq[0] + sq[1] + sq[2] + sq[3];

        int pos = offset_base + off_local;
        int* ob = g_idx + b * N;
        const int pbase = q * QN + t * 32;           // first point of this word
        unsigned m = wd;
        while (m) { const int l = __ffs(m) - 1; m &= m - 1; ob[pos++] = pbase + l; }
    }
    batch_sync(b);                                   // g_idx fully written

    // ================= Phase 5: gather (2 rows/thread, float4 stores) ======
    {
        #pragma unroll 4
        for (int k = 0; k < PPT / 2; k++) {
            const int jr = base + (t + k * TH) * 2;  // first of 2 output rows
            float4* dst = (float4*)(out + ((size_t)b * N + jr) * 6);
            if (nv == 0) {
                const float4 z4 = make_float4(0.f, 0.f, 0.f, 0.f);
                dst[0] = z4; dst[1] = z4; dst[2] = z4;
                continue;
            }
            const int k0 = jr % nv;
            const int k1 = (k0 + 1 == nv) ? 0 : k0 + 1;
            const int s0 = g_idx[(b << 16) + k0];
            const int s1 = g_idx[(b << 16) + k1];
            const float* p0 = pts + ((size_t)(b << 16) + s0) * 6;
            const float* p1 = pts + ((size_t)(b << 16) + s1) * 6;
            const float2 a0 = *(const float2*)p0;
            const float2 a1 = *(const float2*)(p0 + 2);
            const float2 a2 = *(const float2*)(p0 + 4);
            const float2 b0 = *(const float2*)p1;
            const float2 b1 = *(const float2*)(p1 + 2);
            const float2 b2 = *(const float2*)(p1 + 4);
            dst[0] = make_float4(a0.x, a0.y, a1.x, a1.y);
            dst[1] = make_float4(a2.x, a2.y, b0.x, b0.y);
            dst[2] = make_float4(b1.x, b1.y, b2.x, b2.y);
        }
    }
}

extern "C" void kernel_launch(void* const* d_in, const int* in_sizes, int n_in,
                              void* d_out, int out_size) {
    const float* pts = (const float*)d_in[0];
    float* out = (float*)d_out;
    mega_kernel<<<GRID, TH>>>(pts, out);
}

// round 7
// speedup vs baseline: 1.4388x; 1.0692x over previous
#include <cuda_runtime.h>
#include <cstdint>

#define B    64
#define N    65536
#define CPB  4                  // CTAs per batch
#define GRID (B * CPB)          // 256, all resident (148 SMs x 2)
#define TH   512
#define QN   (N / CPB)          // 16384 points per CTA
#define PPT  (QN / TH)          // 32 points per thread
#define WQ   (QN / 32)          // 512 bitmask words per quarter (== TH)

// ---- __device__ scratch (allocation-free rule) ----
__device__ float2   g_xy[B * N];            // packed xy (32 MB)
__device__ float    g_z[B * N];             // packed z  (16 MB)
__device__ float    g_pv[2 * GRID];         // partial argmax values (double-buffered)
__device__ int      g_pi[2 * GRID];         // partial argmax indices (global ids)
__device__ int      g_idx[B * N];           // compacted kept indices
__device__ int      g_qtot[GRID];           // per-quarter keep counts
__device__ unsigned g_cnt[B];               // per-batch barrier counters
__device__ unsigned g_gen[B];               // per-batch barrier generations

// Per-batch barrier among the CPB CTAs of one batch. All CTAs resident.
__device__ __forceinline__ void batch_sync(int b) {
    __syncthreads();
    if (threadIdx.x == 0) {
        __threadfence();
        const unsigned gen = atomicAdd(&g_gen[b], 0u);
        if (atomicAdd(&g_cnt[b], 1u) == CPB - 1u) {
            atomicExch(&g_cnt[b], 0u);
            __threadfence();
            atomicAdd(&g_gen[b], 1u);                 // release
        } else {
            while (atomicAdd(&g_gen[b], 0u) == gen) { __nanosleep(32); }
        }
        __threadfence();
    }
    __syncthreads();
}

// warp argmax: value desc, index asc on ties
__device__ __forceinline__ void warp_argmax(float& best, int& bi) {
    #pragma unroll
    for (int o = 16; o; o >>= 1) {
        const float v = __shfl_down_sync(0xffffffffu, best, o);
        const int   j = __shfl_down_sync(0xffffffffu, bi,   o);
        if (v > best || (v == best && j < bi)) { best = v; bi = j; }
    }
}

// block partial argmax (512 threads) -> g_pv/g_pi[buf*GRID + cta]
__device__ __forceinline__ void block_partial(float best, int bi, int buf,
                                              float* sv, int* si) {
    const int t = threadIdx.x, lane = t & 31, w = t >> 5;
    warp_argmax(best, bi);
    if (lane == 0) { sv[w] = best; si[w] = bi; }
    __syncthreads();
    if (t < 16) {
        best = sv[t]; bi = si[t];
        #pragma unroll
        for (int o = 8; o; o >>= 1) {
            const float v = __shfl_down_sync(0xffffu, best, o);
            const int   j = __shfl_down_sync(0xffffu, bi,   o);
            if (v > best || (v == best && j < bi)) { best = v; bi = j; }
        }
        if (t == 0) {
            g_pv[buf * GRID + blockIdx.x] = best;
            g_pi[buf * GRID + blockIdx.x] = bi;
        }
    }
    __syncthreads();   // sv/si reused by later phases
}

__global__ __launch_bounds__(TH, 2) void mega_kernel(const float* __restrict__ pts,
                                                     float* __restrict__ out) {
    const int cta  = blockIdx.x;
    const int b    = cta / CPB;
    const int q    = cta % CPB;
    const int base = q * QN;                         // batch-local start
    const float* P = pts + (size_t)b * N * 6;
    const int t = threadIdx.x;
    const int lane = t & 31, w = t >> 5;

    __shared__ float4   sc[4];
    __shared__ float    sv[16];
    __shared__ int      si[16];
    __shared__ int      swarp[16];
    __shared__ int      sq[CPB];
    __shared__ unsigned sw[WQ];                      // mask words (2 KB)

    // ================= Phase 0: pack + dist^2 to center 0 =================
    const float c0x = P[0], c0y = P[1], c0z = P[2];  // center 0 = point 0
    if (t == 0) sc[0] = make_float4(c0x, c0y, c0z, 0.f);
    {
        float best = -1.0f; int bi = 0;
        #pragma unroll 8
        for (int k = 0; k < PPT; k++) {
            const int il = base + t + k * TH;        // strided: coalesced
            const int gi = b * N + il;
            const float* p = P + (size_t)il * 6;
            const float2 xy = *(const float2*)p;     // rows 24B -> 8B aligned
            const float  z  = p[2];
            g_xy[gi] = xy;
            g_z[gi]  = z;
            const float dx = xy.x - c0x, dy = xy.y - c0y, dz = z - c0z;
            const float md = dx * dx + dy * dy + dz * dz;
            if (md > best) { best = md; bi = gi; }   // strict >: min-index ties
        }
        block_partial(best, bi, /*buf=*/0, sv, si);
    }
    batch_sync(b);

    // ========== Phases 1,2: FPS steps; s==3 only resolves center 3 =========
    for (int s = 1; s <= 3; s++) {
        const int rbuf = (s - 1) & 1;                // buffer written by phase s-1
        if (t == 0) {
            float bv = g_pv[rbuf * GRID + b * CPB];
            int   bj = g_pi[rbuf * GRID + b * CPB];
            #pragma unroll
            for (int i = 1; i < CPB; i++) {
                const float v = g_pv[rbuf * GRID + b * CPB + i];
                const int   j = g_pi[rbuf * GRID + b * CPB + i];
                if (v > bv || (v == bv && j < bj)) { bv = v; bj = j; }
            }
            const float2 xy = g_xy[bj];
            sc[s] = make_float4(xy.x, xy.y, g_z[bj], 0.f);
        }
        __syncthreads();
        if (s == 3) break;                           // all 4 centers known

        float best = -1.0f; int bi = 0;
        #pragma unroll 4
        for (int k = 0; k < PPT; k++) {
            const int gi = b * N + base + t + k * TH;
            const float2 xy = g_xy[gi];
            const float  z  = g_z[gi];
            float md = 1e10f;
            for (int cc = 0; cc <= s; cc++) {
                const float dx = xy.x - sc[cc].x;
                const float dy = xy.y - sc[cc].y;
                const float dz = z    - sc[cc].z;
                md = fminf(md, dx * dx + dy * dy + dz * dz);
            }
            if (md > best) { best = md; bi = gi; }
        }
        block_partial(best, bi, /*buf=*/s & 1, sv, si);
        batch_sync(b);
    }

    // ====== Phase 3: keep bitmask -> smem words (no global round-trip) =====
    {
        const float4 cc0 = sc[0], cc1 = sc[1], cc2 = sc[2], cc3 = sc[3];
        #pragma unroll 4
        for (int k = 0; k < PPT; k++) {
            const int gi = b * N + base + t + k * TH;  // warp lanes consecutive
            const float2 xy = g_xy[gi];
            const float  z  = g_z[gi];
            float dx = xy.x - cc0.x, dy = xy.y - cc0.y, dz = z - cc0.z;
            float md = fminf(1e10f, dx * dx + dy * dy + dz * dz);
            dx = xy.x - cc1.x; dy = xy.y - cc1.y; dz = z - cc1.z;
            md = fminf(md, dx * dx + dy * dy + dz * dz);
            dx = xy.x - cc2.x; dy = xy.y - cc2.y; dz = z - cc2.z;
            md = fminf(md, dx * dx + dy * dy + dz * dz);
            dx = xy.x - cc3.x; dy = xy.y - cc3.y; dz = z - cc3.z;
            md = fminf(md, dx * dx + dy * dy + dz * dz);
            const bool keep = (__fsqrt_rn(md) >= 0.2f);
            const unsigned wd = __ballot_sync(0xffffffffu, keep);
            if (lane == 0) sw[w + k * 16] = wd;       // quarter-local word id
        }
    }
    __syncthreads();                                  // block-local only

    // ======== Phase 4: stable compaction, split 4 ways per batch ===========
    int nv;                                          // num_valid (kept in regs)
    {
        const unsigned wd = sw[t];                   // word t of this quarter
        const int cnt = __popc(wd);

        int inc = cnt;
        #pragma unroll
        for (int o = 1; o < 32; o <<= 1) {
            const int u = __shfl_up_sync(0xffffffffu, inc, o);
            if (lane >= o) inc += u;
        }
        if (lane == 31) swarp[w] = inc;
        __syncthreads();
        if (t < 16) {
            int v2 = swarp[t];
            #pragma unroll
            for (int o = 1; o < 16; o <<= 1) {
                const int u = __shfl_up_sync(0xffffu, v2, o);
                if (t >= o) v2 += u;
            }
            swarp[t] = v2;
        }
        __syncthreads();
        const int off_local = inc - cnt + (w ? swarp[w - 1] : 0);
        if (t == 0) g_qtot[cta] = swarp[15];         // publish quarter total
        batch_sync(b);

        if (t < CPB) sq[t] = g_qtot[b * CPB + t];
        __syncthreads();
        int offset_base = 0;
        for (int i = 0; i < q; i++) offset_base += sq[i];
        nv = sq[0] + sq[1] + sq[2] + sq[3];

        int pos = offset_base + off_local;
        int* ob = g_idx + b * N;
        const int pbase = q * QN + t * 32;           // first point of this word
        unsigned m = wd;
        while (m) { const int l2 = __ffs(m) - 1; m &= m - 1; ob[pos++] = pbase + l2; }
    }
    batch_sync(b);                                   // g_idx fully written

    // ====== Phase 5: gather with per-warp consecutive-run fast path =========
    {
        const int* ob = g_idx + (b << 16);
        #pragma unroll 1
        for (int k = 0; k < PPT / 2; k++) {
            const int jr0 = base + (w * 32 + k * TH) * 2;   // warp's first row (64 rows)
            bool fast = false; int sfirst = 0;
            if (nv > 0) {
                const int kf = jr0 % nv;
                if (kf + 63 < nv) {
                    int sA = 0, sB = 0;
                    if (lane == 0) { sA = ob[kf]; sB = ob[kf + 63]; }
                    sA = __shfl_sync(0xffffffffu, sA, 0);
                    sB = __shfl_sync(0xffffffffu, sB, 0);
                    fast = (sB - sA == 63);           // 64 consecutive sources
                    sfirst = sA;
                }
            }
            if (fast) {
                // contiguous 1536B block copy, fully coalesced float2s
                const float2* s2 = (const float2*)(pts + ((size_t)(b << 16) + sfirst) * 6);
                float2* d2 = (float2*)(out + ((size_t)b * N + jr0) * 6);
                #pragma unroll
                for (int m = 0; m < 6; m++) d2[m * 32 + lane] = s2[m * 32 + lane];
            } else {
                const int jr = jr0 + lane * 2;              // this lane's 2 rows
                float4* dst = (float4*)(out + ((size_t)b * N + jr) * 6);
                if (nv == 0) {
                    const float4 z4 = make_float4(0.f, 0.f, 0.f, 0.f);
                    dst[0] = z4; dst[1] = z4; dst[2] = z4;
                    continue;
                }
                const int k0 = jr % nv;
                const int k1 = (k0 + 1 == nv) ? 0 : k0 + 1;
                const int s0 = ob[k0];
                const int s1 = ob[k1];
                const float* p0 = pts + ((size_t)(b << 16) + s0) * 6;
                const float* p1 = pts + ((size_t)(b << 16) + s1) * 6;
                const float2 a0 = *(const float2*)p0;
                const float2 a1 = *(const float2*)(p0 + 2);
                const float2 a2 = *(const float2*)(p0 + 4);
                const float2 b0 = *(const float2*)p1;
                const float2 b1 = *(const float2*)(p1 + 2);
                const float2 b2 = *(const float2*)(p1 + 4);
                dst[0] = make_float4(a0.x, a0.y, a1.x, a1.y);
                dst[1] = make_float4(a2.x, a2.y, b0.x, b0.y);
                dst[2] = make_float4(b1.x, b1.y, b2.x, b2.y);
            }
        }
    }
}

extern "C" void kernel_launch(void* const* d_in, const int* in_sizes, int n_in,
                              void* d_out, int out_size) {
    const float* pts = (const float*)d_in[0];
    float* out = (float*)d_out;
    mega_kernel<<<GRID, TH>>>(pts, out);
}